// round 5
// baseline (speedup 1.0000x reference)
#include <cuda_runtime.h>

typedef unsigned long long u64;
#define NSL 384
#define SLC 12800
#define ESL 160000
#define VN  400
#define CH  32
#define LL  12

__device__ __align__(16) float g_Xt [NSL*SLC];
__device__ __align__(16) float g_X1 [NSL*SLC];
__device__ __align__(16) float g_X2 [NSL*SLC];
__device__ __align__(16) float g_H1a[NSL*SLC];
__device__ __align__(16) float g_H1b[NSL*SLC];
__device__ __align__(16) float g_H2a[NSL*SLC];
__device__ __align__(16) float g_H2b[NSL*SLC];
__device__ __align__(16) float g_R1 [NSL*VN];
__device__ __align__(16) float g_R2 [NSL*VN];
__device__ __align__(16) float g_E  [NSL*ESL];
__device__ __align__(16) float g_ET [NSL*ESL];

__device__ __forceinline__ void fma2(u64 &d, u64 a, u64 b) {
    asm("fma.rn.f32x2 %0, %1, %2, %0;" : "+l"(d) : "l"(a), "l"(b));
}
__device__ __forceinline__ u64 pk2(float x) {
    u64 r; asm("mov.b64 %0, {%1, %1};" : "=l"(r) : "f"(x)); return r;
}
__device__ __forceinline__ float2 up2(u64 a) {
    float2 r; asm("mov.b64 {%0, %1}, %2;" : "=f"(r.x), "=f"(r.y) : "l"(a)); return r;
}

// transpose x -> g_Xt[s][c][v],  s = n*12+l
__global__ __launch_bounds__(256) void k_tr(const float* __restrict__ x) {
    int od = blockIdx.x * 256 + threadIdx.x;
    if (od >= NSL * SLC) return;
    int s = od / SLC, rem = od % SLC;
    int c = rem / VN, v = rem - c * VN;
    int n = s / LL, l = s - n * LL;
    g_Xt[od] = x[((size_t)(n * CH + c) * VN + v) * LL + l];
}

// X1 = tanh(W1 Xt + b1), X2 = tanh(W2 Xt + b2)
__global__ __launch_bounds__(256) void k_conv(const float* __restrict__ w1,
                                              const float* __restrict__ b1,
                                              const float* __restrict__ w2,
                                              const float* __restrict__ b2) {
    __shared__ float w1s[1024], w2s[1024], b1s[32], b2s[32];
    int s = blockIdx.x, t = threadIdx.x;
    for (int i = t; i < 1024; i += 256) { w1s[i] = w1[i]; w2s[i] = w2[i]; }
    if (t < 32) { b1s[t] = b1[t]; b2s[t] = b2[t]; }
    __syncthreads();
    const float* xt = g_Xt + (size_t)s * SLC;
    for (int i = t; i < SLC; i += 256) {
        int c = i / VN, v = i - c * VN;
        float a1 = b1s[c], a2 = b2s[c];
        #pragma unroll
        for (int k = 0; k < 32; k++) {
            float xv = xt[k * VN + v];
            a1 += w1s[c * 32 + k] * xv;
            a2 += w2s[c * 32 + k] * xv;
        }
        g_X1[(size_t)s * SLC + i] = tanhf(a1);
        g_X2[(size_t)s * SLC + i] = tanhf(a2);
    }
}

// Eo[s][v][w] = exp(sum_k A[s][k][v]*B[s][k][w]); Ro[s][v] = row sums.
// grid (13, NSL), block 256.  Exact row ownership per warp -> deterministic.
__global__ __launch_bounds__(256) void k2(const float* __restrict__ A,
                                          const float* __restrict__ B,
                                          float* __restrict__ Eo,
                                          float* __restrict__ Ro) {
    __shared__ u64 As[1024];
    int s = blockIdx.y, vbase = blockIdx.x * 32;
    int t = threadIdx.x, lam = t & 31, wp = t >> 5;
    for (int i = t; i < 1024; i += 256) {
        int k = i >> 5, vl = i & 31, v = vbase + vl;
        As[i] = pk2(v < VN ? A[(size_t)s * SLC + k * VN + v] : 0.f);
    }
    __syncthreads();
    u64 acc[4][4][2];
    #pragma unroll
    for (int i = 0; i < 4; i++)
        #pragma unroll
        for (int j = 0; j < 4; j++) { acc[i][j][0] = 0; acc[i][j][1] = 0; }
    const ulonglong2* Bq = (const ulonglong2*)(B + (size_t)s * SLC);
    int q[4]; bool qa[4];
    #pragma unroll
    for (int j = 0; j < 4; j++) { q[j] = lam + 32 * j; qa[j] = (q[j] < 100); }
    int q3s = qa[3] ? q[3] : 0;
    #pragma unroll 4
    for (int k = 0; k < 32; k++) {
        ulonglong2 bb[4];
        bb[0] = Bq[k * 100 + q[0]];
        bb[1] = Bq[k * 100 + q[1]];
        bb[2] = Bq[k * 100 + q[2]];
        bb[3] = Bq[k * 100 + q3s];
        #pragma unroll
        for (int i = 0; i < 4; i++) {
            u64 a = As[k * 32 + wp * 4 + i];
            #pragma unroll
            for (int j = 0; j < 4; j++) {
                fma2(acc[i][j][0], a, bb[j].x);
                fma2(acc[i][j][1], a, bb[j].y);
            }
        }
    }
    float rs[4] = {0.f, 0.f, 0.f, 0.f};
    #pragma unroll
    for (int i = 0; i < 4; i++) {
        int v = vbase + wp * 4 + i;
        #pragma unroll
        for (int j = 0; j < 4; j++) {
            if (!qa[j]) continue;
            float2 p0 = up2(acc[i][j][0]), p1 = up2(acc[i][j][1]);
            float4 e;
            e.x = __expf(p0.x); e.y = __expf(p0.y);
            e.z = __expf(p1.x); e.w = __expf(p1.y);
            rs[i] += (e.x + e.y) + (e.z + e.w);
            if (v < VN)
                ((float4*)(Eo + (size_t)s * ESL + (size_t)v * VN))[q[j]] = e;
        }
    }
    #pragma unroll
    for (int i = 0; i < 4; i++)
        #pragma unroll
        for (int o = 16; o > 0; o >>= 1)
            rs[i] += __shfl_xor_sync(0xffffffffu, rs[i], o);
    if (lam == 0)
        #pragma unroll
        for (int i = 0; i < 4; i++) {
            int v = vbase + wp * 4 + i;
            if (v < VN) Ro[(size_t)s * VN + v] = rs[i];
        }
}

// Hout[s][c][w] = 0.05*Xt + 0.95*sum_v (Hin[c][v]/Rm[v]) * Em[v][w]
// grid (2, NSL), block 256, dyn smem = (VN + SLC)*4 = 52800 B
__global__ __launch_bounds__(256) void kd(const float* __restrict__ Em,
                                          const float* __restrict__ Rm,
                                          const float* __restrict__ Hin,
                                          float* __restrict__ Hout) {
    extern __shared__ float sm[];
    float* rinv = sm;
    float* Hs   = sm + VN;
    int s = blockIdx.y, wt = blockIdx.x;
    int t = threadIdx.x, lam = t & 31, wp = t >> 5;
    for (int i = t; i < VN; i += 256) rinv[i] = 1.0f / Rm[(size_t)s * VN + i];
    __syncthreads();
    for (int i = t; i < SLC; i += 256)
        Hs[i] = Hin[(size_t)s * SLC + i] * rinv[i % VN];
    __syncthreads();

    bool ok1 = (lam + 32) < 50;
    int q0 = wt * 50 + lam;
    int q1 = wt * 50 + (ok1 ? lam + 32 : 0);
    int c0 = wp * 4;
    u64 acc[4][2][2];
    #pragma unroll
    for (int i = 0; i < 4; i++) {
        acc[i][0][0] = 0; acc[i][0][1] = 0;
        acc[i][1][0] = 0; acc[i][1][1] = 0;
    }
    const ulonglong2* Eq = (const ulonglong2*)(Em + (size_t)s * ESL);
    #pragma unroll 2
    for (int v = 0; v < VN; v++) {
        ulonglong2 e0 = Eq[(size_t)v * 100 + q0];
        ulonglong2 e1 = Eq[(size_t)v * 100 + q1];
        #pragma unroll
        for (int i = 0; i < 4; i++) {
            u64 h = pk2(Hs[(c0 + i) * VN + v]);
            fma2(acc[i][0][0], h, e0.x);
            fma2(acc[i][0][1], h, e0.y);
            fma2(acc[i][1][0], h, e1.x);
            fma2(acc[i][1][1], h, e1.y);
        }
    }
    #pragma unroll
    for (int i = 0; i < 4; i++) {
        int c = c0 + i;
        const float4* xt = (const float4*)(g_Xt + (size_t)s * SLC + c * VN);
        float4* ho = (float4*)(Hout + (size_t)s * SLC + c * VN);
        float4 xv = xt[q0];
        float2 p0 = up2(acc[i][0][0]), p1 = up2(acc[i][0][1]);
        float4 r;
        r.x = 0.05f * xv.x + 0.95f * p0.x;
        r.y = 0.05f * xv.y + 0.95f * p0.y;
        r.z = 0.05f * xv.z + 0.95f * p1.x;
        r.w = 0.05f * xv.w + 0.95f * p1.y;
        ho[q0] = r;
        if (ok1) {
            float4 xw = xt[q1];
            float2 s0 = up2(acc[i][1][0]), s1 = up2(acc[i][1][1]);
            float4 r2;
            r2.x = 0.05f * xw.x + 0.95f * s0.x;
            r2.y = 0.05f * xw.y + 0.95f * s0.y;
            r2.z = 0.05f * xw.z + 0.95f * s1.x;
            r2.w = 0.05f * xw.w + 0.95f * s1.y;
            ho[q1] = r2;
        }
    }
}

// out = b1+b2 + (Wm1x+Wm2x)Xt + Wm1a*H1a + Wm1b*H1b + Wm2a*H2a + Wm2b*H2b
__global__ __launch_bounds__(256) void k_mlp(const float* __restrict__ w1,
                                             const float* __restrict__ b1,
                                             const float* __restrict__ w2,
                                             const float* __restrict__ b2,
                                             float* __restrict__ out) {
    __shared__ float wxc[1024], wa1[2048], wa2[2048], bs[32];
    int s = blockIdx.x, t = threadIdx.x;
    int n = s / LL, l = s - n * LL;
    for (int i = t; i < 1024; i += 256) {
        int o = i >> 5, c = i & 31;
        wxc[i] = w1[o * 96 + c] + w2[o * 96 + c];
    }
    for (int i = t; i < 2048; i += 256) {
        int o = i >> 6, c = i & 63;
        wa1[i] = w1[o * 96 + 32 + c];
        wa2[i] = w2[o * 96 + 32 + c];
    }
    if (t < 32) bs[t] = b1[t] + b2[t];
    __syncthreads();
    size_t sb = (size_t)s * SLC;
    for (int i = t; i < SLC; i += 256) {
        int o = i / VN, v = i - o * VN;
        float a = bs[o];
        #pragma unroll
        for (int c = 0; c < 32; c++) {
            a += wxc[o * 32 + c] * g_Xt [sb + c * VN + v];
            a += wa1[o * 64 + c]      * g_H1a[sb + c * VN + v];
            a += wa1[o * 64 + 32 + c] * g_H1b[sb + c * VN + v];
            a += wa2[o * 64 + c]      * g_H2a[sb + c * VN + v];
            a += wa2[o * 64 + 32 + c] * g_H2b[sb + c * VN + v];
        }
        out[((size_t)(n * CH + o) * VN + v) * LL + l] = a;
    }
}

extern "C" void kernel_launch(void* const* d_in, const int* in_sizes, int n_in,
                              void* d_out, int out_size) {
    const float* x     = (const float*)d_in[0];
    const float* wl1   = (const float*)d_in[1];
    const float* bl1   = (const float*)d_in[2];
    const float* wl2   = (const float*)d_in[3];
    const float* bl2   = (const float*)d_in[4];
    const float* wm1   = (const float*)d_in[5];
    const float* bm1   = (const float*)d_in[6];
    const float* wm2   = (const float*)d_in[7];
    const float* bm2   = (const float*)d_in[8];
    float* out = (float*)d_out;

    static bool attr_done = false;
    if (!attr_done) {
        cudaFuncSetAttribute(kd, cudaFuncAttributeMaxDynamicSharedMemorySize,
                             (VN + SLC) * 4);
        attr_done = true;
    }

    float *E, *ET, *R1, *R2, *X1, *X2, *Xt, *H1a, *H1b, *H2a, *H2b;
    cudaGetSymbolAddress((void**)&E,  g_E);
    cudaGetSymbolAddress((void**)&ET, g_ET);
    cudaGetSymbolAddress((void**)&R1, g_R1);
    cudaGetSymbolAddress((void**)&R2, g_R2);
    cudaGetSymbolAddress((void**)&X1, g_X1);
    cudaGetSymbolAddress((void**)&X2, g_X2);
    cudaGetSymbolAddress((void**)&Xt, g_Xt);
    cudaGetSymbolAddress((void**)&H1a, g_H1a);
    cudaGetSymbolAddress((void**)&H1b, g_H1b);
    cudaGetSymbolAddress((void**)&H2a, g_H2a);
    cudaGetSymbolAddress((void**)&H2b, g_H2b);

    k_tr<<<(NSL * SLC + 255) / 256, 256>>>(x);
    k_conv<<<NSL, 256>>>(wl1, bl1, wl2, bl2);
    k2<<<dim3(13, NSL), 256>>>(X1, X2, E,  R1);
    k2<<<dim3(13, NSL), 256>>>(X2, X1, ET, R2);
    int dsm = (VN + SLC) * 4;
    kd<<<dim3(2, NSL), 256, dsm>>>(E,  R1, Xt,  H1a);
    kd<<<dim3(2, NSL), 256, dsm>>>(E,  R1, H1a, H1b);
    kd<<<dim3(2, NSL), 256, dsm>>>(ET, R2, Xt,  H2a);
    kd<<<dim3(2, NSL), 256, dsm>>>(ET, R2, H2a, H2b);
    k_mlp<<<NSL, 256>>>(wm1, bm1, wm2, bm2, out);
}

// round 6
// speedup vs baseline: 1.0701x; 1.0701x over previous
#include <cuda_runtime.h>

typedef unsigned long long u64;
#define NSL 384
#define SLC 12800
#define ESL 160000
#define VN  400
#define CH  32
#define LL  12

__device__ __align__(16) float g_Xt [NSL*SLC];
__device__ __align__(16) float g_X1 [NSL*SLC];
__device__ __align__(16) float g_X2 [NSL*SLC];
__device__ __align__(16) float g_H1a[NSL*SLC];
__device__ __align__(16) float g_H1b[NSL*SLC];
__device__ __align__(16) float g_H2a[NSL*SLC];
__device__ __align__(16) float g_H2b[NSL*SLC];
__device__ __align__(16) float g_R1 [NSL*VN];
__device__ __align__(16) float g_R2 [NSL*VN];
__device__ __align__(16) float g_E  [NSL*ESL];
__device__ __align__(16) float g_ET [NSL*ESL];

__device__ __forceinline__ void fma2(u64 &d, u64 a, u64 b) {
    asm("fma.rn.f32x2 %0, %1, %2, %0;" : "+l"(d) : "l"(a), "l"(b));
}
__device__ __forceinline__ u64 pk2(float x) {
    u64 r; asm("mov.b64 %0, {%1, %1};" : "=l"(r) : "f"(x)); return r;
}
__device__ __forceinline__ float2 up2(u64 a) {
    float2 r; asm("mov.b64 {%0, %1}, %2;" : "=f"(r.x), "=f"(r.y) : "l"(a)); return r;
}

// transpose x -> g_Xt[s][c][v],  s = n*12+l
__global__ __launch_bounds__(256) void k_tr(const float* __restrict__ x) {
    int od = blockIdx.x * 256 + threadIdx.x;
    if (od >= NSL * SLC) return;
    int s = od / SLC, rem = od % SLC;
    int c = rem / VN, v = rem - c * VN;
    int n = s / LL, l = s - n * LL;
    g_Xt[od] = x[((size_t)(n * CH + c) * VN + v) * LL + l];
}

// X1 = tanh(W1 Xt + b1), X2 = tanh(W2 Xt + b2)
__global__ __launch_bounds__(256) void k_conv(const float* __restrict__ w1,
                                              const float* __restrict__ b1,
                                              const float* __restrict__ w2,
                                              const float* __restrict__ b2) {
    __shared__ float w1s[1024], w2s[1024], b1s[32], b2s[32];
    int s = blockIdx.x, t = threadIdx.x;
    for (int i = t; i < 1024; i += 256) { w1s[i] = w1[i]; w2s[i] = w2[i]; }
    if (t < 32) { b1s[t] = b1[t]; b2s[t] = b2[t]; }
    __syncthreads();
    const float* xt = g_Xt + (size_t)s * SLC;
    for (int i = t; i < SLC; i += 256) {
        int c = i / VN, v = i - c * VN;
        float a1 = b1s[c], a2 = b2s[c];
        #pragma unroll
        for (int k = 0; k < 32; k++) {
            float xv = xt[k * VN + v];
            a1 += w1s[c * 32 + k] * xv;
            a2 += w2s[c * 32 + k] * xv;
        }
        g_X1[(size_t)s * SLC + i] = tanhf(a1);
        g_X2[(size_t)s * SLC + i] = tanhf(a2);
    }
}

// Eo[s][v][w] = exp(sum_k A[s][k][v]*B[s][k][w]); Ro[s][v] = row sums.
// grid (13, NSL), block 256.  2 CTAs/SM forced; double-buffered B prefetch.
__global__ __launch_bounds__(256, 2) void k2(const float* __restrict__ A,
                                             const float* __restrict__ B,
                                             float* __restrict__ Eo,
                                             float* __restrict__ Ro) {
    __shared__ u64 As[1024];
    int s = blockIdx.y, vbase = blockIdx.x * 32;
    int t = threadIdx.x, lam = t & 31, wp = t >> 5;
    for (int i = t; i < 1024; i += 256) {
        int k = i >> 5, vl = i & 31, v = vbase + vl;
        As[i] = pk2(v < VN ? A[(size_t)s * SLC + k * VN + v] : 0.f);
    }
    __syncthreads();
    u64 acc[4][4][2];
    #pragma unroll
    for (int i = 0; i < 4; i++)
        #pragma unroll
        for (int j = 0; j < 4; j++) { acc[i][j][0] = 0; acc[i][j][1] = 0; }
    const ulonglong2* Bq = (const ulonglong2*)(B + (size_t)s * SLC);
    int q[4]; bool qa[4];
    #pragma unroll
    for (int j = 0; j < 4; j++) { q[j] = lam + 32 * j; qa[j] = (q[j] < 100); }
    int q3s = qa[3] ? q[3] : 0;

    ulonglong2 cur[4], nxt[4];
    cur[0] = Bq[q[0]]; cur[1] = Bq[q[1]]; cur[2] = Bq[q[2]]; cur[3] = Bq[q3s];
    #pragma unroll 4
    for (int k = 0; k < 32; k++) {
        if (k < 31) {
            const ulonglong2* Bk = Bq + (size_t)(k + 1) * 100;
            nxt[0] = Bk[q[0]]; nxt[1] = Bk[q[1]];
            nxt[2] = Bk[q[2]]; nxt[3] = Bk[q3s];
        }
        #pragma unroll
        for (int i = 0; i < 4; i++) {
            u64 a = As[k * 32 + wp * 4 + i];
            #pragma unroll
            for (int j = 0; j < 4; j++) {
                fma2(acc[i][j][0], a, cur[j].x);
                fma2(acc[i][j][1], a, cur[j].y);
            }
        }
        #pragma unroll
        for (int j = 0; j < 4; j++) cur[j] = nxt[j];
    }
    float rs[4] = {0.f, 0.f, 0.f, 0.f};
    #pragma unroll
    for (int i = 0; i < 4; i++) {
        int v = vbase + wp * 4 + i;
        #pragma unroll
        for (int j = 0; j < 4; j++) {
            if (!qa[j]) continue;
            float2 p0 = up2(acc[i][j][0]), p1 = up2(acc[i][j][1]);
            float4 e;
            e.x = __expf(p0.x); e.y = __expf(p0.y);
            e.z = __expf(p1.x); e.w = __expf(p1.y);
            rs[i] += (e.x + e.y) + (e.z + e.w);
            if (v < VN)
                ((float4*)(Eo + (size_t)s * ESL + (size_t)v * VN))[q[j]] = e;
        }
    }
    #pragma unroll
    for (int i = 0; i < 4; i++)
        #pragma unroll
        for (int o = 16; o > 0; o >>= 1)
            rs[i] += __shfl_xor_sync(0xffffffffu, rs[i], o);
    if (lam == 0)
        #pragma unroll
        for (int i = 0; i < 4; i++) {
            int v = vbase + wp * 4 + i;
            if (v < VN) Ro[(size_t)s * VN + v] = rs[i];
        }
}

// Hout[s][c][w] = 0.05*Xt + 0.95*sum_v (Hin[c][v]/Rm[v]) * Em[v][w]
// grid (2, NSL), block 256, dyn smem = (VN + SLC)*4.  Batch-4 E prefetch.
__global__ __launch_bounds__(256, 4) void kd(const float* __restrict__ Em,
                                             const float* __restrict__ Rm,
                                             const float* __restrict__ Hin,
                                             float* __restrict__ Hout) {
    extern __shared__ float sm[];
    float* rinv = sm;
    float* Hs   = sm + VN;
    int s = blockIdx.y, wt = blockIdx.x;
    int t = threadIdx.x, lam = t & 31, wp = t >> 5;
    for (int i = t; i < VN; i += 256) rinv[i] = 1.0f / Rm[(size_t)s * VN + i];
    __syncthreads();
    for (int i = t; i < SLC; i += 256)
        Hs[i] = Hin[(size_t)s * SLC + i] * rinv[i % VN];
    __syncthreads();

    bool ok1 = (lam + 32) < 50;
    int q0 = wt * 50 + lam;
    int q1 = wt * 50 + (ok1 ? lam + 32 : 0);
    int c0 = wp * 4;
    u64 acc[4][2][2];
    #pragma unroll
    for (int i = 0; i < 4; i++) {
        acc[i][0][0] = 0; acc[i][0][1] = 0;
        acc[i][1][0] = 0; acc[i][1][1] = 0;
    }
    const ulonglong2* Eq = (const ulonglong2*)(Em + (size_t)s * ESL);
    for (int vb = 0; vb < VN; vb += 4) {
        ulonglong2 E0[4], E1[4];
        #pragma unroll
        for (int j = 0; j < 4; j++) {
            E0[j] = Eq[(size_t)(vb + j) * 100 + q0];
            E1[j] = Eq[(size_t)(vb + j) * 100 + q1];
        }
        #pragma unroll
        for (int j = 0; j < 4; j++) {
            #pragma unroll
            for (int i = 0; i < 4; i++) {
                u64 h = pk2(Hs[(c0 + i) * VN + vb + j]);
                fma2(acc[i][0][0], h, E0[j].x);
                fma2(acc[i][0][1], h, E0[j].y);
                fma2(acc[i][1][0], h, E1[j].x);
                fma2(acc[i][1][1], h, E1[j].y);
            }
        }
    }
    #pragma unroll
    for (int i = 0; i < 4; i++) {
        int c = c0 + i;
        const float4* xt = (const float4*)(g_Xt + (size_t)s * SLC + c * VN);
        float4* ho = (float4*)(Hout + (size_t)s * SLC + c * VN);
        float4 xv = xt[q0];
        float2 p0 = up2(acc[i][0][0]), p1 = up2(acc[i][0][1]);
        float4 r;
        r.x = 0.05f * xv.x + 0.95f * p0.x;
        r.y = 0.05f * xv.y + 0.95f * p0.y;
        r.z = 0.05f * xv.z + 0.95f * p1.x;
        r.w = 0.05f * xv.w + 0.95f * p1.y;
        ho[q0] = r;
        if (ok1) {
            float4 xw = xt[q1];
            float2 s0 = up2(acc[i][1][0]), s1 = up2(acc[i][1][1]);
            float4 r2;
            r2.x = 0.05f * xw.x + 0.95f * s0.x;
            r2.y = 0.05f * xw.y + 0.95f * s0.y;
            r2.z = 0.05f * xw.z + 0.95f * s1.x;
            r2.w = 0.05f * xw.w + 0.95f * s1.y;
            ho[q1] = r2;
        }
    }
}

// out = b1+b2 + (Wm1x+Wm2x)Xt + Wm1a*H1a + Wm1b*H1b + Wm2a*H2a + Wm2b*H2b
// float4-vectorized over v.
__global__ __launch_bounds__(256) void k_mlp(const float* __restrict__ w1,
                                             const float* __restrict__ b1,
                                             const float* __restrict__ w2,
                                             const float* __restrict__ b2,
                                             float* __restrict__ out) {
    __shared__ float wxc[1024], wa1[2048], wa2[2048], bs[32];
    int s = blockIdx.x, t = threadIdx.x;
    int n = s / LL, l = s - n * LL;
    for (int i = t; i < 1024; i += 256) {
        int o = i >> 5, c = i & 31;
        wxc[i] = w1[o * 96 + c] + w2[o * 96 + c];
    }
    for (int i = t; i < 2048; i += 256) {
        int o = i >> 6, c = i & 63;
        wa1[i] = w1[o * 96 + 32 + c];
        wa2[i] = w2[o * 96 + 32 + c];
    }
    if (t < 32) bs[t] = b1[t] + b2[t];
    __syncthreads();
    size_t sb = (size_t)s * SLC;
    const float4* Xt4 = (const float4*)(g_Xt  + sb);
    const float4* A14 = (const float4*)(g_H1a + sb);
    const float4* B14 = (const float4*)(g_H1b + sb);
    const float4* A24 = (const float4*)(g_H2a + sb);
    const float4* B24 = (const float4*)(g_H2b + sb);
    for (int qd = t; qd < 3200; qd += 256) {
        int o = qd / 100, vq = qd - o * 100;
        float bz = bs[o];
        float4 a; a.x = bz; a.y = bz; a.z = bz; a.w = bz;
        #pragma unroll 8
        for (int c = 0; c < 32; c++) {
            int idx = c * 100 + vq;
            float4 xv = Xt4[idx];
            float w = wxc[o * 32 + c];
            a.x += w * xv.x; a.y += w * xv.y; a.z += w * xv.z; a.w += w * xv.w;
            float4 h1 = A14[idx];
            w = wa1[o * 64 + c];
            a.x += w * h1.x; a.y += w * h1.y; a.z += w * h1.z; a.w += w * h1.w;
            float4 h1b = B14[idx];
            w = wa1[o * 64 + 32 + c];
            a.x += w * h1b.x; a.y += w * h1b.y; a.z += w * h1b.z; a.w += w * h1b.w;
            float4 h2 = A24[idx];
            w = wa2[o * 64 + c];
            a.x += w * h2.x; a.y += w * h2.y; a.z += w * h2.z; a.w += w * h2.w;
            float4 h2b = B24[idx];
            w = wa2[o * 64 + 32 + c];
            a.x += w * h2b.x; a.y += w * h2b.y; a.z += w * h2b.z; a.w += w * h2b.w;
        }
        int v = vq * 4;
        size_t ob = ((size_t)(n * CH + o) * VN + v) * LL + l;
        out[ob]          = a.x;
        out[ob + LL]     = a.y;
        out[ob + 2 * LL] = a.z;
        out[ob + 3 * LL] = a.w;
    }
}

extern "C" void kernel_launch(void* const* d_in, const int* in_sizes, int n_in,
                              void* d_out, int out_size) {
    const float* x   = (const float*)d_in[0];
    const float* wl1 = (const float*)d_in[1];
    const float* bl1 = (const float*)d_in[2];
    const float* wl2 = (const float*)d_in[3];
    const float* bl2 = (const float*)d_in[4];
    const float* wm1 = (const float*)d_in[5];
    const float* bm1 = (const float*)d_in[6];
    const float* wm2 = (const float*)d_in[7];
    const float* bm2 = (const float*)d_in[8];
    float* out = (float*)d_out;

    static bool attr_done = false;
    if (!attr_done) {
        cudaFuncSetAttribute(kd, cudaFuncAttributeMaxDynamicSharedMemorySize,
                             (VN + SLC) * 4);
        attr_done = true;
    }

    float *E, *ET, *R1, *R2, *X1, *X2, *Xt, *H1a, *H1b, *H2a, *H2b;
    cudaGetSymbolAddress((void**)&E,  g_E);
    cudaGetSymbolAddress((void**)&ET, g_ET);
    cudaGetSymbolAddress((void**)&R1, g_R1);
    cudaGetSymbolAddress((void**)&R2, g_R2);
    cudaGetSymbolAddress((void**)&X1, g_X1);
    cudaGetSymbolAddress((void**)&X2, g_X2);
    cudaGetSymbolAddress((void**)&Xt, g_Xt);
    cudaGetSymbolAddress((void**)&H1a, g_H1a);
    cudaGetSymbolAddress((void**)&H1b, g_H1b);
    cudaGetSymbolAddress((void**)&H2a, g_H2a);
    cudaGetSymbolAddress((void**)&H2b, g_H2b);

    k_tr<<<(NSL * SLC + 255) / 256, 256>>>(x);
    k_conv<<<NSL, 256>>>(wl1, bl1, wl2, bl2);
    k2<<<dim3(13, NSL), 256>>>(X1, X2, E,  R1);
    k2<<<dim3(13, NSL), 256>>>(X2, X1, ET, R2);
    int dsm = (VN + SLC) * 4;
    kd<<<dim3(2, NSL), 256, dsm>>>(E,  R1, Xt,  H1a);
    kd<<<dim3(2, NSL), 256, dsm>>>(E,  R1, H1a, H1b);
    kd<<<dim3(2, NSL), 256, dsm>>>(ET, R2, Xt,  H2a);
    kd<<<dim3(2, NSL), 256, dsm>>>(ET, R2, H2a, H2b);
    k_mlp<<<NSL, 256>>>(wm1, bm1, wm2, bm2, out);
}

// round 8
// speedup vs baseline: 1.5259x; 1.4259x over previous
#include <cuda_runtime.h>

typedef unsigned long long u64;
#define NSL 384
#define SLC 12800
#define ESL 160000
#define VN  400
#define CH  32
#define LL  12

__device__ __align__(16) float g_Xt [NSL*SLC];
__device__ __align__(16) float g_X1 [NSL*SLC];
__device__ __align__(16) float g_X2 [NSL*SLC];
__device__ __align__(16) float g_H1a[NSL*SLC];
__device__ __align__(16) float g_H1b[NSL*SLC];
__device__ __align__(16) float g_H2a[NSL*SLC];
__device__ __align__(16) float g_H2b[NSL*SLC];
__device__ __align__(16) float g_R1 [NSL*VN];
__device__ __align__(16) float g_R2 [NSL*VN];
__device__ __align__(16) float g_E  [NSL*ESL];
__device__ __align__(16) float g_ET [NSL*ESL];

__device__ __forceinline__ void fma2(u64 &d, u64 a, u64 b) {
    asm("fma.rn.f32x2 %0, %1, %2, %0;" : "+l"(d) : "l"(a), "l"(b));
}
__device__ __forceinline__ u64 pk2(float x) {
    u64 r; asm("mov.b64 %0, {%1, %1};" : "=l"(r) : "f"(x)); return r;
}
__device__ __forceinline__ float2 up2(u64 a) {
    float2 r; asm("mov.b64 {%0, %1}, %2;" : "=f"(r.x), "=f"(r.y) : "l"(a)); return r;
}

// transpose x -> g_Xt[s][c][v],  s = n*12+l
__global__ __launch_bounds__(256) void k_tr(const float* __restrict__ x) {
    int od = blockIdx.x * 256 + threadIdx.x;
    if (od >= NSL * SLC) return;
    int s = od / SLC, rem = od % SLC;
    int c = rem / VN, v = rem - c * VN;
    int n = s / LL, l = s - n * LL;
    g_Xt[od] = x[((size_t)(n * CH + c) * VN + v) * LL + l];
}

// X1 = tanh(W1 Xt + b1), X2 = tanh(W2 Xt + b2)
__global__ __launch_bounds__(256) void k_conv(const float* __restrict__ w1,
                                              const float* __restrict__ b1,
                                              const float* __restrict__ w2,
                                              const float* __restrict__ b2) {
    __shared__ float w1s[1024], w2s[1024], b1s[32], b2s[32];
    int s = blockIdx.x, t = threadIdx.x;
    for (int i = t; i < 1024; i += 256) { w1s[i] = w1[i]; w2s[i] = w2[i]; }
    if (t < 32) { b1s[t] = b1[t]; b2s[t] = b2[t]; }
    __syncthreads();
    const float* xt = g_Xt + (size_t)s * SLC;
    for (int i = t; i < SLC; i += 256) {
        int c = i / VN, v = i - c * VN;
        float a1 = b1s[c], a2 = b2s[c];
        #pragma unroll
        for (int k = 0; k < 32; k++) {
            float xv = xt[k * VN + v];
            a1 += w1s[c * 32 + k] * xv;
            a2 += w2s[c * 32 + k] * xv;
        }
        g_X1[(size_t)s * SLC + i] = tanhf(a1);
        g_X2[(size_t)s * SLC + i] = tanhf(a2);
    }
}

// Eo[s][v][w] = exp(sum_k A[s][k][v]*B[s][k][w]); Ro[s][v] = row sums (over w).
// grid (13, NSL), block 256. Thread t<200 owns w-pair (2t,2t+1) x 32 v-rows.
__global__ __launch_bounds__(256, 2) void k2(const float* __restrict__ A,
                                             const float* __restrict__ B,
                                             float* __restrict__ Eo,
                                             float* __restrict__ Ro) {
    __shared__ u64 As2[1024];      // [k][vl], packed pairs, 8KB
    __shared__ float red[256];     // [warp][v] partial row sums
    int s = blockIdx.y, vbase = blockIdx.x * 32;
    int t = threadIdx.x, lam = t & 31, wp = t >> 5;
    for (int i = t; i < 1024; i += 256) {
        int k = i >> 5, vl = i & 31, v = vbase + vl;
        As2[i] = pk2(v < VN ? A[(size_t)s * SLC + k * VN + v] : 0.f);
    }
    __syncthreads();
    bool act = (t < 200);
    int w2 = act ? 2 * t : 0;
    u64 acc[32];
    #pragma unroll
    for (int i = 0; i < 32; i++) acc[i] = 0;
    const float* Bb = B + (size_t)s * SLC;
    #pragma unroll 2
    for (int k = 0; k < 32; k++) {
        u64 b = *(const u64*)(Bb + k * VN + w2);
        #pragma unroll
        for (int vp = 0; vp < 16; vp++) {
            ulonglong2 a = *(const ulonglong2*)&As2[k * 32 + 2 * vp];
            fma2(acc[2 * vp],     a.x, b);
            fma2(acc[2 * vp + 1], a.y, b);
        }
    }
    int vcnt = VN - vbase; if (vcnt > 32) vcnt = 32;
    float prs[32];
    float* Erow = Eo + (size_t)s * ESL;
    #pragma unroll
    for (int v = 0; v < 32; v++) {
        float2 p = up2(acc[v]);
        float2 e;
        e.x = __expf(p.x); e.y = __expf(p.y);
        prs[v] = act ? (e.x + e.y) : 0.f;
        if (act && v < vcnt)
            *(float2*)(Erow + (size_t)(vbase + v) * VN + w2) = e;
    }
    #pragma unroll
    for (int v = 0; v < 32; v++) {
        #pragma unroll
        for (int o = 16; o > 0; o >>= 1)
            prs[v] += __shfl_xor_sync(0xffffffffu, prs[v], o);
    }
    if (lam == 0) {
        #pragma unroll
        for (int v = 0; v < 32; v++) red[wp * 32 + v] = prs[v];
    }
    __syncthreads();
    if (t < vcnt) {
        float sum = 0.f;
        #pragma unroll
        for (int w = 0; w < 8; w++) sum += red[w * 32 + t];
        Ro[(size_t)s * VN + vbase + t] = sum;
    }
}

// Hout[s][c][w] = 0.05*Xt + 0.95*sum_v (Hin[c][v]/Rm[v]) * Em[v][w]
// grid NSL, block 256. Thread t<200 owns w-pair x all 32 channels.
// dyn smem = 400*4 + 32*400*8 = 104000 B (rinv + packed H).
__global__ __launch_bounds__(256, 2) void kd(const float* __restrict__ Em,
                                             const float* __restrict__ Rm,
                                             const float* __restrict__ Hin,
                                             float* __restrict__ Hout) {
    extern __shared__ float smf[];
    float* rinv = smf;                       // 400 floats
    u64* hs2 = (u64*)(smf + VN);             // [c][v] packed pairs
    int s = blockIdx.x, t = threadIdx.x;
    for (int i = t; i < VN; i += 256) rinv[i] = 1.0f / Rm[(size_t)s * VN + i];
    __syncthreads();
    for (int i = t; i < SLC; i += 256)
        hs2[i] = pk2(Hin[(size_t)s * SLC + i] * rinv[i % VN]);
    __syncthreads();

    bool act = (t < 200);
    int w2 = act ? 2 * t : 0;
    u64 acc[32];
    #pragma unroll
    for (int c = 0; c < 32; c++) acc[c] = 0;
    const float* Eb = Em + (size_t)s * ESL;
    #pragma unroll 2
    for (int v = 0; v < VN; v += 2) {
        u64 e0 = *(const u64*)(Eb + (size_t)v * VN + w2);
        u64 e1 = *(const u64*)(Eb + (size_t)(v + 1) * VN + w2);
        #pragma unroll
        for (int c = 0; c < 32; c++) {
            ulonglong2 h = *(const ulonglong2*)&hs2[c * VN + v];
            fma2(acc[c], h.x, e0);
            fma2(acc[c], h.y, e1);
        }
    }
    if (act) {
        const float* Xb = g_Xt + (size_t)s * SLC;
        float* Ob = Hout + (size_t)s * SLC;
        #pragma unroll
        for (int c = 0; c < 32; c++) {
            float2 xv = *(const float2*)(Xb + c * VN + w2);
            float2 p = up2(acc[c]);
            float2 r;
            r.x = 0.05f * xv.x + 0.95f * p.x;
            r.y = 0.05f * xv.y + 0.95f * p.y;
            *(float2*)(Ob + c * VN + w2) = r;
        }
    }
}

// out = b1+b2 + (Wm1x+Wm2x)Xt + Wm1a*H1a + Wm1b*H1b + Wm2a*H2a + Wm2b*H2b
__global__ __launch_bounds__(256) void k_mlp(const float* __restrict__ w1,
                                             const float* __restrict__ b1,
                                             const float* __restrict__ w2,
                                             const float* __restrict__ b2,
                                             float* __restrict__ out) {
    __shared__ float wxc[1024], wa1[2048], wa2[2048], bs[32];
    int s = blockIdx.x, t = threadIdx.x;
    int n = s / LL, l = s - n * LL;
    for (int i = t; i < 1024; i += 256) {
        int o = i >> 5, c = i & 31;
        wxc[i] = w1[o * 96 + c] + w2[o * 96 + c];
    }
    for (int i = t; i < 2048; i += 256) {
        int o = i >> 6, c = i & 63;
        wa1[i] = w1[o * 96 + 32 + c];
        wa2[i] = w2[o * 96 + 32 + c];
    }
    if (t < 32) bs[t] = b1[t] + b2[t];
    __syncthreads();
    size_t sb = (size_t)s * SLC;
    const float4* Xt4 = (const float4*)(g_Xt  + sb);
    const float4* A14 = (const float4*)(g_H1a + sb);
    const float4* B14 = (const float4*)(g_H1b + sb);
    const float4* A24 = (const float4*)(g_H2a + sb);
    const float4* B24 = (const float4*)(g_H2b + sb);
    for (int qd = t; qd < 3200; qd += 256) {
        int o = qd / 100, vq = qd - o * 100;
        float bz = bs[o];
        float4 a; a.x = bz; a.y = bz; a.z = bz; a.w = bz;
        #pragma unroll 8
        for (int c = 0; c < 32; c++) {
            int idx = c * 100 + vq;
            float4 xv = Xt4[idx];
            float w = wxc[o * 32 + c];
            a.x += w * xv.x; a.y += w * xv.y; a.z += w * xv.z; a.w += w * xv.w;
            float4 h1 = A14[idx];
            w = wa1[o * 64 + c];
            a.x += w * h1.x; a.y += w * h1.y; a.z += w * h1.z; a.w += w * h1.w;
            float4 h1b = B14[idx];
            w = wa1[o * 64 + 32 + c];
            a.x += w * h1b.x; a.y += w * h1b.y; a.z += w * h1b.z; a.w += w * h1b.w;
            float4 h2 = A24[idx];
            w = wa2[o * 64 + c];
            a.x += w * h2.x; a.y += w * h2.y; a.z += w * h2.z; a.w += w * h2.w;
            float4 h2b = B24[idx];
            w = wa2[o * 64 + 32 + c];
            a.x += w * h2b.x; a.y += w * h2b.y; a.z += w * h2b.z; a.w += w * h2b.w;
        }
        int v = vq * 4;
        size_t ob = ((size_t)(n * CH + o) * VN + v) * LL + l;
        out[ob]          = a.x;
        out[ob + LL]     = a.y;
        out[ob + 2 * LL] = a.z;
        out[ob + 3 * LL] = a.w;
    }
}

extern "C" void kernel_launch(void* const* d_in, const int* in_sizes, int n_in,
                              void* d_out, int out_size) {
    const float* x   = (const float*)d_in[0];
    const float* wl1 = (const float*)d_in[1];
    const float* bl1 = (const float*)d_in[2];
    const float* wl2 = (const float*)d_in[3];
    const float* bl2 = (const float*)d_in[4];
    const float* wm1 = (const float*)d_in[5];
    const float* bm1 = (const float*)d_in[6];
    const float* wm2 = (const float*)d_in[7];
    const float* bm2 = (const float*)d_in[8];
    float* out = (float*)d_out;

    const int dsm = VN * 4 + SLC * 8;   // 104000 B
    static bool attr_done = false;
    if (!attr_done) {
        cudaFuncSetAttribute(kd, cudaFuncAttributeMaxDynamicSharedMemorySize, dsm);
        attr_done = true;
    }

    float *E, *ET, *R1, *R2, *X1, *X2, *Xt, *H1a, *H1b, *H2a, *H2b;
    cudaGetSymbolAddress((void**)&E,  g_E);
    cudaGetSymbolAddress((void**)&ET, g_ET);
    cudaGetSymbolAddress((void**)&R1, g_R1);
    cudaGetSymbolAddress((void**)&R2, g_R2);
    cudaGetSymbolAddress((void**)&X1, g_X1);
    cudaGetSymbolAddress((void**)&X2, g_X2);
    cudaGetSymbolAddress((void**)&Xt, g_Xt);
    cudaGetSymbolAddress((void**)&H1a, g_H1a);
    cudaGetSymbolAddress((void**)&H1b, g_H1b);
    cudaGetSymbolAddress((void**)&H2a, g_H2a);
    cudaGetSymbolAddress((void**)&H2b, g_H2b);

    k_tr<<<(NSL * SLC + 255) / 256, 256>>>(x);
    k_conv<<<NSL, 256>>>(wl1, bl1, wl2, bl2);
    k2<<<dim3(13, NSL), 256>>>(X1, X2, E,  R1);
    k2<<<dim3(13, NSL), 256>>>(X2, X1, ET, R2);
    kd<<<NSL, 256, dsm>>>(E,  R1, Xt,  H1a);
    kd<<<NSL, 256, dsm>>>(E,  R1, H1a, H1b);
    kd<<<NSL, 256, dsm>>>(ET, R2, Xt,  H2a);
    kd<<<NSL, 256, dsm>>>(ET, R2, H2a, H2b);
    k_mlp<<<NSL, 256>>>(wm1, bm1, wm2, bm2, out);
}

// round 9
// speedup vs baseline: 1.7066x; 1.1184x over previous
#include <cuda_runtime.h>

typedef unsigned long long u64;
#define NSL 384
#define SLC 12800
#define ESL 160000
#define VN  400
#define CH  32
#define LL  12

__device__ __align__(16) float g_Xt [NSL*SLC];
__device__ __align__(16) float g_X1 [NSL*SLC];
__device__ __align__(16) float g_X2 [NSL*SLC];
__device__ __align__(16) float g_H1a[NSL*SLC];
__device__ __align__(16) float g_H1b[NSL*SLC];
__device__ __align__(16) float g_H2a[NSL*SLC];
__device__ __align__(16) float g_H2b[NSL*SLC];
__device__ __align__(16) float g_R1 [NSL*VN];
__device__ __align__(16) float g_R2 [NSL*VN];
__device__ __align__(16) float g_E  [NSL*ESL];
__device__ __align__(16) float g_ET [NSL*ESL];

__device__ __forceinline__ void fma2(u64 &d, u64 a, u64 b) {
    asm("fma.rn.f32x2 %0, %1, %2, %0;" : "+l"(d) : "l"(a), "l"(b));
}
__device__ __forceinline__ u64 pk2(float x) {
    u64 r; asm("mov.b64 %0, {%1, %1};" : "=l"(r) : "f"(x)); return r;
}
__device__ __forceinline__ float2 up2(u64 a) {
    float2 r; asm("mov.b64 {%0, %1}, %2;" : "=f"(r.x), "=f"(r.y) : "l"(a)); return r;
}

// transpose x -> g_Xt[s][c][v],  s = n*12+l
__global__ __launch_bounds__(256) void k_tr(const float* __restrict__ x) {
    int od = blockIdx.x * 256 + threadIdx.x;
    if (od >= NSL * SLC) return;
    int s = od / SLC, rem = od % SLC;
    int c = rem / VN, v = rem - c * VN;
    int n = s / LL, l = s - n * LL;
    g_Xt[od] = x[((size_t)(n * CH + c) * VN + v) * LL + l];
}

// X1 = tanh(W1 Xt + b1), X2 = tanh(W2 Xt + b2)
__global__ __launch_bounds__(256) void k_conv(const float* __restrict__ w1,
                                              const float* __restrict__ b1,
                                              const float* __restrict__ w2,
                                              const float* __restrict__ b2) {
    __shared__ float w1s[1024], w2s[1024], b1s[32], b2s[32];
    int s = blockIdx.x, t = threadIdx.x;
    for (int i = t; i < 1024; i += 256) { w1s[i] = w1[i]; w2s[i] = w2[i]; }
    if (t < 32) { b1s[t] = b1[t]; b2s[t] = b2[t]; }
    __syncthreads();
    const float* xt = g_Xt + (size_t)s * SLC;
    for (int i = t; i < SLC; i += 256) {
        int c = i / VN, v = i - c * VN;
        float a1 = b1s[c], a2 = b2s[c];
        #pragma unroll
        for (int k = 0; k < 32; k++) {
            float xv = xt[k * VN + v];
            a1 += w1s[c * 32 + k] * xv;
            a2 += w2s[c * 32 + k] * xv;
        }
        g_X1[(size_t)s * SLC + i] = tanhf(a1);
        g_X2[(size_t)s * SLC + i] = tanhf(a2);
    }
}

// Fused E-builder: z=0 -> E=exp(X1^T X2), rowsums R1; z=1 -> ET, R2.
// grid (13, NSL, 2), block 128. Thread t<100 owns w-quad (4t..4t+3) x 32 v.
__global__ __launch_bounds__(128, 2) void k2(const float* __restrict__ X1p,
                                             const float* __restrict__ X2p,
                                             float* __restrict__ Eo1,
                                             float* __restrict__ Ro1,
                                             float* __restrict__ Eo2,
                                             float* __restrict__ Ro2) {
    __shared__ u64 As2[1024];     // [k][vl] packed pairs
    __shared__ float red[128];    // [warp][v]
    int s = blockIdx.y, vbase = blockIdx.x * 32, z = blockIdx.z;
    const float* A = z ? X2p : X1p;
    const float* B = z ? X1p : X2p;
    float* Eo = z ? Eo2 : Eo1;
    float* Ro = z ? Ro2 : Ro1;
    int t = threadIdx.x, lam = t & 31, wp = t >> 5;
    for (int i = t; i < 1024; i += 128) {
        int k = i >> 5, vl = i & 31, v = vbase + vl;
        As2[i] = pk2(v < VN ? A[(size_t)s * SLC + k * VN + v] : 0.f);
    }
    __syncthreads();
    bool act = (t < 100);
    int w4 = act ? 4 * t : 0;
    u64 acc[32][2];
    #pragma unroll
    for (int v = 0; v < 32; v++) { acc[v][0] = 0; acc[v][1] = 0; }
    const float* Bb = B + (size_t)s * SLC;
    #pragma unroll 2
    for (int k = 0; k < 32; k++) {
        ulonglong2 bq = *(const ulonglong2*)(Bb + k * VN + w4);
        #pragma unroll
        for (int vp = 0; vp < 16; vp++) {
            ulonglong2 a = *(const ulonglong2*)&As2[k * 32 + 2 * vp];
            fma2(acc[2 * vp][0],     a.x, bq.x);
            fma2(acc[2 * vp][1],     a.x, bq.y);
            fma2(acc[2 * vp + 1][0], a.y, bq.x);
            fma2(acc[2 * vp + 1][1], a.y, bq.y);
        }
    }
    int vcnt = VN - vbase; if (vcnt > 32) vcnt = 32;
    float* Erow = Eo + (size_t)s * ESL;
    float prs[32];
    #pragma unroll
    for (int v = 0; v < 32; v++) {
        float2 p0 = up2(acc[v][0]), p1 = up2(acc[v][1]);
        float4 e;
        e.x = __expf(p0.x); e.y = __expf(p0.y);
        e.z = __expf(p1.x); e.w = __expf(p1.y);
        prs[v] = act ? (e.x + e.y) + (e.z + e.w) : 0.f;
        if (act && v < vcnt)
            *(float4*)(Erow + (size_t)(vbase + v) * VN + w4) = e;
    }
    #pragma unroll
    for (int v = 0; v < 32; v++) {
        #pragma unroll
        for (int o = 16; o > 0; o >>= 1)
            prs[v] += __shfl_xor_sync(0xffffffffu, prs[v], o);
    }
    if (lam == 0) {
        #pragma unroll
        for (int v = 0; v < 32; v++) red[wp * 32 + v] = prs[v];
    }
    __syncthreads();
    if (t < vcnt) {
        float sum = red[t] + red[32 + t] + red[64 + t] + red[96 + t];
        Ro[(size_t)s * VN + vbase + t] = sum;
    }
}

// Fused diffusion step for both directions (blockIdx.y).
// Hout[c][w] = 0.05*Xt + 0.95*sum_v (Hin[c][v]/Rm[v]) * Em[v][w]
// grid (NSL, 2), block 128. Thread t<100 owns w-quad x all 32 channels.
// dyn smem = 400*4 + 12800*8 = 104000 B.
__global__ __launch_bounds__(128, 2) void kd(const float* __restrict__ E1,
                                             const float* __restrict__ Rr1,
                                             const float* __restrict__ E2,
                                             const float* __restrict__ Rr2,
                                             const float* __restrict__ Hi1,
                                             const float* __restrict__ Hi2,
                                             float* __restrict__ Ho1,
                                             float* __restrict__ Ho2) {
    extern __shared__ float smf[];
    float* rinv = smf;                // 400
    u64* hs2 = (u64*)(smf + VN);      // [c][v] packed pairs
    int s = blockIdx.x, t = threadIdx.x, side = blockIdx.y;
    const float* Em  = side ? E2  : E1;
    const float* Rm  = side ? Rr2 : Rr1;
    const float* Hin = side ? Hi2 : Hi1;
    float* Hout      = side ? Ho2 : Ho1;
    for (int i = t; i < VN; i += 128) rinv[i] = 1.0f / Rm[(size_t)s * VN + i];
    __syncthreads();
    for (int i = t; i < SLC; i += 128)
        hs2[i] = pk2(Hin[(size_t)s * SLC + i] * rinv[i % VN]);
    __syncthreads();

    bool act = (t < 100);
    int w4 = act ? 4 * t : 0;
    u64 acc[32][2];
    #pragma unroll
    for (int c = 0; c < 32; c++) { acc[c][0] = 0; acc[c][1] = 0; }
    const float* Eb = Em + (size_t)s * ESL;
    #pragma unroll 2
    for (int v = 0; v < VN; v += 2) {
        ulonglong2 e0 = *(const ulonglong2*)(Eb + (size_t)v * VN + w4);
        ulonglong2 e1 = *(const ulonglong2*)(Eb + (size_t)(v + 1) * VN + w4);
        #pragma unroll
        for (int c = 0; c < 32; c++) {
            ulonglong2 h = *(const ulonglong2*)&hs2[c * VN + v];
            fma2(acc[c][0], h.x, e0.x);
            fma2(acc[c][1], h.x, e0.y);
            fma2(acc[c][0], h.y, e1.x);
            fma2(acc[c][1], h.y, e1.y);
        }
    }
    if (act) {
        const float* Xb = g_Xt + (size_t)s * SLC;
        float* Ob = Hout + (size_t)s * SLC;
        #pragma unroll
        for (int c = 0; c < 32; c++) {
            float4 xv = *(const float4*)(Xb + c * VN + w4);
            float2 p0 = up2(acc[c][0]), p1 = up2(acc[c][1]);
            float4 r;
            r.x = 0.05f * xv.x + 0.95f * p0.x;
            r.y = 0.05f * xv.y + 0.95f * p0.y;
            r.z = 0.05f * xv.z + 0.95f * p1.x;
            r.w = 0.05f * xv.w + 0.95f * p1.y;
            *(float4*)(Ob + c * VN + w4) = r;
        }
    }
}

// out = b1+b2 + (Wm1x+Wm2x)Xt + Wm1a*H1a + Wm1b*H1b + Wm2a*H2a + Wm2b*H2b
__global__ __launch_bounds__(256) void k_mlp(const float* __restrict__ w1,
                                             const float* __restrict__ b1,
                                             const float* __restrict__ w2,
                                             const float* __restrict__ b2,
                                             float* __restrict__ out) {
    __shared__ float wxc[1024], wa1[2048], wa2[2048], bs[32];
    int s = blockIdx.x, t = threadIdx.x;
    int n = s / LL, l = s - n * LL;
    for (int i = t; i < 1024; i += 256) {
        int o = i >> 5, c = i & 31;
        wxc[i] = w1[o * 96 + c] + w2[o * 96 + c];
    }
    for (int i = t; i < 2048; i += 256) {
        int o = i >> 6, c = i & 63;
        wa1[i] = w1[o * 96 + 32 + c];
        wa2[i] = w2[o * 96 + 32 + c];
    }
    if (t < 32) bs[t] = b1[t] + b2[t];
    __syncthreads();
    size_t sb = (size_t)s * SLC;
    const float4* Xt4 = (const float4*)(g_Xt  + sb);
    const float4* A14 = (const float4*)(g_H1a + sb);
    const float4* B14 = (const float4*)(g_H1b + sb);
    const float4* A24 = (const float4*)(g_H2a + sb);
    const float4* B24 = (const float4*)(g_H2b + sb);
    for (int qd = t; qd < 3200; qd += 256) {
        int o = qd / 100, vq = qd - o * 100;
        float bz = bs[o];
        float4 a; a.x = bz; a.y = bz; a.z = bz; a.w = bz;
        #pragma unroll 8
        for (int c = 0; c < 32; c++) {
            int idx = c * 100 + vq;
            float4 xv = Xt4[idx];
            float w = wxc[o * 32 + c];
            a.x += w * xv.x; a.y += w * xv.y; a.z += w * xv.z; a.w += w * xv.w;
            float4 h1 = A14[idx];
            w = wa1[o * 64 + c];
            a.x += w * h1.x; a.y += w * h1.y; a.z += w * h1.z; a.w += w * h1.w;
            float4 h1b = B14[idx];
            w = wa1[o * 64 + 32 + c];
            a.x += w * h1b.x; a.y += w * h1b.y; a.z += w * h1b.z; a.w += w * h1b.w;
            float4 h2 = A24[idx];
            w = wa2[o * 64 + c];
            a.x += w * h2.x; a.y += w * h2.y; a.z += w * h2.z; a.w += w * h2.w;
            float4 h2b = B24[idx];
            w = wa2[o * 64 + 32 + c];
            a.x += w * h2b.x; a.y += w * h2b.y; a.z += w * h2b.z; a.w += w * h2b.w;
        }
        int v = vq * 4;
        size_t ob = ((size_t)(n * CH + o) * VN + v) * LL + l;
        out[ob]          = a.x;
        out[ob + LL]     = a.y;
        out[ob + 2 * LL] = a.z;
        out[ob + 3 * LL] = a.w;
    }
}

extern "C" void kernel_launch(void* const* d_in, const int* in_sizes, int n_in,
                              void* d_out, int out_size) {
    const float* x   = (const float*)d_in[0];
    const float* wl1 = (const float*)d_in[1];
    const float* bl1 = (const float*)d_in[2];
    const float* wl2 = (const float*)d_in[3];
    const float* bl2 = (const float*)d_in[4];
    const float* wm1 = (const float*)d_in[5];
    const float* bm1 = (const float*)d_in[6];
    const float* wm2 = (const float*)d_in[7];
    const float* bm2 = (const float*)d_in[8];
    float* out = (float*)d_out;

    const int dsm = VN * 4 + SLC * 8;   // 104000 B
    static bool attr_done = false;
    if (!attr_done) {
        cudaFuncSetAttribute(kd, cudaFuncAttributeMaxDynamicSharedMemorySize, dsm);
        attr_done = true;
    }

    float *E, *ET, *R1, *R2, *X1, *X2, *Xt, *H1a, *H1b, *H2a, *H2b;
    cudaGetSymbolAddress((void**)&E,  g_E);
    cudaGetSymbolAddress((void**)&ET, g_ET);
    cudaGetSymbolAddress((void**)&R1, g_R1);
    cudaGetSymbolAddress((void**)&R2, g_R2);
    cudaGetSymbolAddress((void**)&X1, g_X1);
    cudaGetSymbolAddress((void**)&X2, g_X2);
    cudaGetSymbolAddress((void**)&Xt, g_Xt);
    cudaGetSymbolAddress((void**)&H1a, g_H1a);
    cudaGetSymbolAddress((void**)&H1b, g_H1b);
    cudaGetSymbolAddress((void**)&H2a, g_H2a);
    cudaGetSymbolAddress((void**)&H2b, g_H2b);

    k_tr<<<(NSL * SLC + 255) / 256, 256>>>(x);
    k_conv<<<NSL, 256>>>(wl1, bl1, wl2, bl2);
    k2<<<dim3(13, NSL, 2), 128>>>(X1, X2, E, R1, ET, R2);
    kd<<<dim3(NSL, 2), 128, dsm>>>(E, R1, ET, R2, Xt,  Xt,  H1a, H2a);
    kd<<<dim3(NSL, 2), 128, dsm>>>(E, R1, ET, R2, H1a, H2a, H1b, H2b);
    k_mlp<<<NSL, 256>>>(wm1, bm1, wm2, bm2, out);
}